// round 11
// baseline (speedup 1.0000x reference)
#include <cuda_runtime.h>
#include <cstdint>

// YoloLoss: pred [B,7,7,30] f32, target [B,7,7,30] f32 -> scalar f32 loss.
// Persistent kernel, 1 CTA/SM, 256 threads split into TWO independent
// 128-thread pipeline groups. Each group owns a private 3-stage TMA-bulk
// ring (mbarrier expect_tx completion) and syncs with a named barrier only,
// so the two groups drift freely and the SM's TMA request stream never has
// an all-stop point (the R9 limiter: one serial wait->compute->refill chain
// per CTA put periodic holes in the DRAM request stream).

#define S7 7
#define CH 30
#define TCELLS 128                        // cells per tile (= threads per group)
#define TILE_FLOATS (TCELLS * CH)         // 3840
#define TILE_BYTES  (TILE_FLOATS * 4)     // 15360
#define STAGE_FLOATS (2 * TILE_FLOATS)    // pred + target
#define STAGE_BYTES  (2 * TILE_BYTES)     // 30720
#define NST 3                             // stages per group
#define NGROUPS 2
#define CPB 256
#define SMEM_BYTES (NGROUPS * NST * STAGE_BYTES)   // 184320
#define NBLOCKS 148                       // 1 CTA/SM
#define MAXBLK 8192

__device__ float g_partials[MAXBLK];
__device__ unsigned int g_ticket = 0;     // returns to 0 after every launch

__device__ __forceinline__ uint32_t smem_u32(const void* p) {
    return (uint32_t)__cvta_generic_to_shared(p);
}
__device__ __forceinline__ void mbar_init(uint32_t mbar, uint32_t count) {
    asm volatile("mbarrier.init.shared.b64 [%0], %1;" :: "r"(mbar), "r"(count) : "memory");
}
__device__ __forceinline__ void mbar_expect_tx(uint32_t mbar, uint32_t bytes) {
    asm volatile("mbarrier.arrive.expect_tx.shared.b64 _, [%0], %1;"
                 :: "r"(mbar), "r"(bytes) : "memory");
}
__device__ __forceinline__ void mbar_wait(uint32_t mbar, uint32_t parity) {
    uint32_t done;
    asm volatile(
        "{\n\t.reg .pred p;\n\t"
        "mbarrier.try_wait.parity.acquire.cta.shared::cta.b64 p, [%1], %2;\n\t"
        "selp.b32 %0, 1, 0, p;\n\t}"
        : "=r"(done) : "r"(mbar), "r"(parity) : "memory");
    if (!done) {
        asm volatile(
            "{\n\t.reg .pred P1;\n\t"
            "W_%=:\n\t"
            "mbarrier.try_wait.parity.acquire.cta.shared::cta.b64 P1, [%0], %1, 0x989680;\n\t"
            "@P1 bra.uni D_%=;\n\t"
            "bra.uni W_%=;\n\t"
            "D_%=:\n\t}"
            :: "r"(mbar), "r"(parity) : "memory");
    }
}
__device__ __forceinline__ void tma_bulk_g2s(uint32_t dst, const void* src,
                                             uint32_t bytes, uint32_t mbar) {
    asm volatile(
        "cp.async.bulk.shared::cta.global.mbarrier::complete_tx::bytes "
        "[%0], [%1], %2, [%3];"
        :: "r"(dst), "l"(src), "r"(bytes), "r"(mbar) : "memory");
}
__device__ __forceinline__ void group_bar(int id) {
    asm volatile("bar.sync %0, %1;" :: "r"(id), "r"(128) : "memory");
}

struct Box { float x1, y1, x2, y2; };

__device__ __forceinline__ Box convert_box(float x, float y, float w, float h,
                                           float gi, float gj) {
    const float STEPF = 1.0f / 7.0f;
    float cx = (x + gi) * STEPF;
    float cy = (y + gj) * STEPF;
    Box b;
    b.x1 = fmaxf(cx - w * 0.5f, 0.0f);
    b.y1 = fmaxf(cy - h * 0.5f, 0.0f);
    b.x2 = fminf(cx + w * 0.5f, 1.0f);
    b.y2 = fminf(cy + h * 0.5f, 1.0f);
    return b;
}

// t = target box, p = pred box — matches reference _iou(tbox, pbox) arg order.
__device__ __forceinline__ float iou_ref(const Box& t, const Box& p) {
    float minx = fmaxf(t.x1, p.x1);
    float miny = fmaxf(t.y1, p.y1);
    float maxx = fminf(t.x2, p.x2);
    float maxy = fminf(t.y2, p.y2);
    float inter = (maxy - miny) * (maxx - minx);   // faithful: no clamp
    float uni = (p.x2 - p.x1) * (p.y2 - p.y1)
              + (t.x2 - t.x1) * (t.y2 - t.y1) - inter;
    return inter > 0.0f ? inter / (uni + 1e-5f) : 0.0f;
}

// Per-cell loss. p/t point at this thread's 30 floats.
__device__ __forceinline__ float cell_loss(const float* p, const float* t, int cellg) {
    int spatial = cellg % (S7 * S7);       // i*7 + j
    float gi = (float)(spatial / S7);      // first spatial axis -> x offset
    float gj = (float)(spatial % S7);      // second spatial axis -> y offset

    Box tb = convert_box(t[0], t[1], t[2], t[3], gi, gj);
    Box p1 = convert_box(p[0], p[1], p[2], p[3], gi, gj);
    Box p2 = convert_box(p[5], p[6], p[7], p[8], gi, gj);

    float iou1 = iou_ref(tb, p1);
    float iou2 = iou_ref(tb, p2);

    bool sel2 = (iou1 <= iou2);
    float conf_t = sel2 ? iou2 : iou1;
    float px = sel2 ? p[5] : p[0];
    float py = sel2 ? p[6] : p[1];
    float pw = sel2 ? p[7] : p[2];
    float ph = sel2 ? p[8] : p[3];
    float pconf = sel2 ? p[9] : p[4];

    float tv4 = t[4];
    float obj   = (tv4 > 0.0f)  ? 1.0f : 0.0f;
    float noobj = (tv4 == 0.0f) ? 1.0f : 0.0f;

    float dx = px - t[0], dy = py - t[1];
    float dw = pw - t[2], dh = ph - t[3];
    float xywh = dx * dx + dy * dy + dw * dw + dh * dh;

    float dcls = 0.0f;
    #pragma unroll
    for (int k = 10; k < CH; k++) {
        float d = p[k] - t[k];
        dcls += d * d;
    }

    float dco = pconf - conf_t;
    float d4 = p[4] - tv4;
    float d9 = p[9] - t[9];
    float dno = d4 * d4 + d9 * d9;

    return obj * (dco * dco) + 0.5f * noobj * dno
         + 5.0f * obj * xywh + obj * dcls;
}

extern __shared__ float dynsmem[];   // NGROUPS * NST stage buffers

__global__ __launch_bounds__(CPB) void yolo_loss_kernel(
    const float* __restrict__ pred,
    const float* __restrict__ target,
    int ncells, int tfull, float invB, float* __restrict__ out)
{
    __shared__ __align__(8) unsigned long long mbar_store[NGROUPS * NST];
    __shared__ float warp_part[CPB / 32];
    __shared__ int s_last;

    const int tid = threadIdx.x;
    const int lane = tid & 31;
    const int wid = tid >> 5;
    const int gtid = tid & 127;            // tid within group
    const int h = tid >> 7;                // group id 0/1
    const int bid = blockIdx.x;
    const int nstreams = 2 * gridDim.x;    // 296 independent tile streams
    const int sid = bid * 2 + h;           // this group's stream id

    const uint32_t mbar0 = smem_u32(mbar_store) + h * NST * 8;
    const uint32_t sbase = smem_u32(dynsmem) + h * NST * STAGE_BYTES;
    float* gbuf = dynsmem + h * NST * STAGE_FLOATS;

    if (tid == 0) {
        #pragma unroll
        for (int s = 0; s < NGROUPS * NST; s++)
            mbar_init(smem_u32(mbar_store) + s * 8, 1);
    }
    __syncthreads();   // all barriers visible before any bulk targets them

    // Prologue: fill this group's pipeline.
    if (gtid == 0) {
        #pragma unroll
        for (int k = 0; k < NST; k++) {
            int t = sid + k * nstreams;
            if (t < tfull) {
                uint32_t mb = mbar0 + k * 8;
                uint32_t dst = sbase + k * STAGE_BYTES;
                mbar_expect_tx(mb, STAGE_BYTES);
                tma_bulk_g2s(dst, pred + (size_t)t * TILE_FLOATS, TILE_BYTES, mb);
                tma_bulk_g2s(dst + TILE_BYTES, target + (size_t)t * TILE_FLOATS,
                             TILE_BYTES, mb);
            }
        }
    }

    float acc = 0.0f;
    int i = 0;
    for (int t = sid; t < tfull; t += nstreams, i++) {
        int s = i % NST;
        uint32_t parity = (uint32_t)((i / NST) & 1);
        uint32_t mb = mbar0 + s * 8;
        mbar_wait(mb, parity);

        const float* buf = gbuf + s * STAGE_FLOATS;
        acc += cell_loss(buf + gtid * CH, buf + TILE_FLOATS + gtid * CH,
                         t * TCELLS + gtid);

        group_bar(1 + h);                  // group done reading stage s
        int tpre = t + NST * nstreams;
        if (tpre < tfull && gtid == 0) {
            uint32_t dst = sbase + s * STAGE_BYTES;
            mbar_expect_tx(mb, STAGE_BYTES);
            tma_bulk_g2s(dst, pred + (size_t)tpre * TILE_FLOATS, TILE_BYTES, mb);
            tma_bulk_g2s(dst + TILE_BYTES, target + (size_t)tpre * TILE_FLOATS,
                         TILE_BYTES, mb);
        }
    }

    // Remainder cells (ncells % TCELLS != 0): block 0 reads straight from gmem.
    if (bid == 0) {
        int cellg = tfull * TCELLS + tid;
        if (cellg < ncells) {
            float pl[CH], tl[CH];
            const float* pg = pred + (size_t)cellg * CH;
            const float* tg = target + (size_t)cellg * CH;
            #pragma unroll
            for (int k = 0; k < CH; k++) { pl[k] = pg[k]; tl[k] = tg[k]; }
            acc += cell_loss(pl, tl, cellg);
        }
    }

    // Warp reduce, then one block reduce.
    #pragma unroll
    for (int o = 16; o > 0; o >>= 1)
        acc += __shfl_xor_sync(0xffffffffu, acc, o);

    if (lane == 0) warp_part[wid] = acc;
    __syncthreads();

    if (tid == 0) {
        float ssum = 0.0f;
        #pragma unroll
        for (int w = 0; w < CPB / 32; w++) ssum += warp_part[w];
        g_partials[bid] = ssum;                    // every slot written: no init needed
        __threadfence();
        unsigned int v = atomicAdd(&g_ticket, 1u);
        s_last = (v == gridDim.x - 1) ? 1 : 0;
    }
    __syncthreads();

    if (s_last) {
        int nblk = gridDim.x;
        float r = 0.0f;
        for (int j = tid; j < nblk; j += CPB)
            r += g_partials[j];
        #pragma unroll
        for (int o = 16; o > 0; o >>= 1)
            r += __shfl_xor_sync(0xffffffffu, r, o);
        if (lane == 0) warp_part[wid] = r;
        __syncthreads();
        if (tid == 0) {
            double total = 0.0;
            #pragma unroll
            for (int w = 0; w < CPB / 32; w++) total += (double)warp_part[w];
            out[0] = (float)(total * (double)invB);
            g_ticket = 0;                          // restore invariant for replays
        }
    }
}

extern "C" void kernel_launch(void* const* d_in, const int* in_sizes, int n_in,
                              void* d_out, int out_size) {
    const float* pred = (const float*)d_in[0];
    const float* target = (const float*)d_in[1];
    float* out = (float*)d_out;

    int ncells = in_sizes[0] / CH;                 // B * 7 * 7
    int B = ncells / (S7 * S7);
    int tfull = ncells / TCELLS;                   // 6272 full tiles for B=16384

    static int attr_set = 0;
    if (!attr_set) {
        cudaFuncSetAttribute(yolo_loss_kernel,
                             cudaFuncAttributeMaxDynamicSharedMemorySize,
                             SMEM_BYTES);
        attr_set = 1;
    }

    yolo_loss_kernel<<<NBLOCKS, CPB, SMEM_BYTES>>>(
        pred, target, ncells, tfull, 1.0f / (float)B, out);
}